// round 15
// baseline (speedup 1.0000x reference)
#include <cuda_runtime.h>
#include <cuda_fp16.h>
#include <cstdint>
#include <math.h>

// ============================================================================
// Problem constants
// ============================================================================
#define BB 4
#define SS 2048
#define DD 1024
#define HH 16
#define HDIM 64
#define MROWS (BB * SS)     /* 8192 */
#define NHEAD (HH * HDIM)   /* 1024 */

// Scratch (device globals: allocation-free)
__device__ __align__(16) __half g_xh[MROWS * DD];        // fp16 x
__device__ __align__(16) __half g_wt[4][DD * NHEAD];     // fp16 W^T (q,k,v,o)
__device__ __align__(16) __half g_qh[MROWS * NHEAD];     // fp16 q
__device__ __align__(16) __half g_kh[MROWS * NHEAD];     // fp16 k
__device__ __align__(16) __half g_vh[MROWS * NHEAD];     // fp16 v
__device__ __align__(16) __half g_ctxh[MROWS * NHEAD];   // fp16 ctx

// ============================================================================
// Helpers
// ============================================================================
__device__ __forceinline__ uint32_t smem_u32(const void* p) {
    uint32_t a;
    asm("{ .reg .u64 t; cvta.to.shared.u64 t, %1; cvt.u32.u64 %0, t; }"
        : "=r"(a) : "l"(p));
    return a;
}

__device__ __forceinline__ uint32_t pack_f16x2(float lo, float hi) {
    uint32_t r;
    asm("cvt.rn.f16x2.f32 %0, %1, %2;" : "=r"(r) : "f"(hi), "f"(lo));
    return r;
}

__device__ __forceinline__ void mma_f16(float* c, const uint32_t* a, const uint32_t* b) {
    asm volatile(
        "mma.sync.aligned.m16n8k16.row.col.f32.f16.f16.f32 "
        "{%0,%1,%2,%3}, {%4,%5,%6,%7}, {%8,%9}, {%0,%1,%2,%3};"
        : "+f"(c[0]), "+f"(c[1]), "+f"(c[2]), "+f"(c[3])
        : "r"(a[0]), "r"(a[1]), "r"(a[2]), "r"(a[3]), "r"(b[0]), "r"(b[1]));
}

__device__ __forceinline__ void ldm_x4(uint32_t* r, uint32_t addr) {
    asm volatile(
        "ldmatrix.sync.aligned.m8n8.x4.shared.b16 {%0,%1,%2,%3}, [%4];"
        : "=r"(r[0]), "=r"(r[1]), "=r"(r[2]), "=r"(r[3]) : "r"(addr));
}

// transposed variant: memory [k][n] row-major -> col-major B fragment
__device__ __forceinline__ void ldm_x4_t(uint32_t* r, uint32_t addr) {
    asm volatile(
        "ldmatrix.sync.aligned.m8n8.x4.trans.shared.b16 {%0,%1,%2,%3}, [%4];"
        : "=r"(r[0]), "=r"(r[1]), "=r"(r[2]), "=r"(r[3]) : "r"(addr));
}

#define CP16(dst, src) \
    asm volatile("cp.async.cg.shared.global [%0], [%1], 16;" \
        :: "r"(dst), "l"(src) : "memory")
#define CP_COMMIT() asm volatile("cp.async.commit_group;" ::: "memory")
#define CP_WAIT1()  asm volatile("cp.async.wait_group 1;" ::: "memory")
#define CP_WAIT0()  asm volatile("cp.async.wait_group 0;" ::: "memory")

// ============================================================================
// Merged prepass (single launch):
//   blocks [0, 8192)        : x fp32 -> fp16 flat (coalesced)
//   blocks [8192, 8192+1024): W{q,k,v,o} fp32 -> fp16 transposed,
//                             64x64 tiles — COALESCED 128B packed writes.
// smem staged [n][k]: scatter-STS bank = tx mod 32 (conflict-free);
// readback LDS.64 of even-word pairs (conflict-free).
// ============================================================================
__global__ void __launch_bounds__(256)
prepass(const float* __restrict__ x, __half* __restrict__ xh,
        const float* __restrict__ Wq, const float* __restrict__ Wk,
        const float* __restrict__ Wv, const float* __restrict__ Wo,
        __half* __restrict__ wt)
{
    __shared__ float tbuf[64][65];
    int bid = blockIdx.x;
    const int tid = threadIdx.x;
    if (bid < 8192) {
        int i = bid * 256 + tid;
        float4 v = ((const float4*)x)[i];
        uint2 o;
        o.x = pack_f16x2(v.x, v.y);
        o.y = pack_f16x2(v.z, v.w);
        ((uint2*)xh)[i] = o;
        return;
    }
    bid -= 8192;
    const int wsel = bid >> 8;             // which weight (256 tiles each)
    const int t    = bid & 255;            // 16x16 grid of 64x64 tiles
    const float* W = (wsel == 0) ? Wq : (wsel == 1) ? Wk : (wsel == 2) ? Wv : Wo;
    __half* Wt = wt + (size_t)wsel * DD * NHEAD;

    const int n0 = (t & 15) * 64, k0 = (t >> 4) * 64;
    const int tx = tid & 63, ty = tid >> 6;        // tx = n-in-tile, ty = k base
    // Load: coalesced 256B row reads, transposed into smem [n][k]
    #pragma unroll
    for (int i = 0; i < 64; i += 4)
        tbuf[tx][ty + i] = W[(size_t)(k0 + ty + i) * 1024 + n0 + tx];
    __syncthreads();
    // Store: packed fp16 pairs, 128B coalesced rows of Wt[n][k]
    const int c = tid & 31, r = tid >> 5;          // c = k-pair, r = n base
    uint32_t* Wt32 = (uint32_t*)Wt;
    #pragma unroll
    for (int i = 0; i < 64; i += 8) {
        const int nr = r + i;
        Wt32[(size_t)(n0 + nr) * 512 + (k0 >> 1) + c] =
            pack_f16x2(tbuf[nr][2 * c], tbuf[nr][2 * c + 1]);
    }
}

// ============================================================================
// FP16 GEMM core — BK=64 (R14 exact).
// CTA 128x128, 8 warps (2Mx4N), warp tile 64x32, m16n8k16, 3 stages.
// ============================================================================
#define GBM 128
#define GBN 128
#define G_STR 36   /* b32 words per smem row: 64 halves (32 w) + 4 pad */
#define G_AWORDS (GBM * G_STR)
#define G_STAGE_BYTES (2 * G_AWORDS * 4)     /* 36864 */
#define G_NSTG 3
#define GSMEM (G_NSTG * G_STAGE_BYTES)       /* 110592 */

__device__ __forceinline__ void
gemm_body(char* smraw, const __half* __restrict__ A, const __half* __restrict__ Wt,
          const float* __restrict__ bias,
          float* __restrict__ Cf, __half* __restrict__ Ch,
          float scale, int outHalf, int bx, int by)
{
    const uint32_t smb = smem_u32(smraw);

    const int tid  = threadIdx.x;
    const int lane = tid & 31;
    const int wid  = tid >> 5;
    const int wm   = wid & 1;
    const int wn   = wid >> 1;
    const int gid  = lane >> 2;
    const int tig  = lane & 3;
    const int m0   = by * GBM;
    const int n0   = bx * GBN;

    float acc[4][4][4];
    #pragma unroll
    for (int i = 0; i < 4; ++i)
        #pragma unroll
        for (int j = 0; j < 4; ++j)
            #pragma unroll
            for (int r = 0; r < 4; ++r) acc[i][j][r] = 0.f;

    const __half* Ag = A  + (size_t)m0 * 1024;
    const __half* Wg = Wt + (size_t)n0 * 1024;

    auto load_stage = [&](int s, int kt) {
        const uint32_t as = smb + (uint32_t)s * G_STAGE_BYTES;
        const uint32_t bs = as + G_AWORDS * 4;
        #pragma unroll
        for (int i = 0; i < 4; ++i) {
            int idx = tid + i * 256;
            int r = idx >> 3, c = (idx & 7) << 3;   // c in halves
            CP16(as + (uint32_t)(r * G_STR * 4 + c * 2),
                 Ag + (size_t)r * 1024 + kt * 64 + c);
            CP16(bs + (uint32_t)(r * G_STR * 4 + c * 2),
                 Wg + (size_t)r * 1024 + kt * 64 + c);
        }
    };

    load_stage(0, 0); CP_COMMIT();
    load_stage(1, 1); CP_COMMIT();

    int st = 0;
    for (int kt = 0; kt < 16; ++kt) {
        CP_WAIT1();
        __syncthreads();

        if (kt + 2 < 16) {
            int sn = st + 2; if (sn >= 3) sn -= 3;
            load_stage(sn, kt + 2);
        }
        CP_COMMIT();

        const uint32_t* a32 = (const uint32_t*)(smraw + st * G_STAGE_BYTES);
        const uint32_t* b32 = a32 + G_AWORDS;

        #pragma unroll
        for (int k16 = 0; k16 < 4; ++k16) {
            uint32_t a[4][4], b[4][2];
            #pragma unroll
            for (int i = 0; i < 4; ++i) {
                const uint32_t* ap = a32 + (wm * 64 + i * 16 + gid) * G_STR
                                         + k16 * 8 + tig;
                a[i][0] = ap[0];
                a[i][1] = ap[8 * G_STR];
                a[i][2] = ap[4];
                a[i][3] = ap[8 * G_STR + 4];
            }
            #pragma unroll
            for (int j = 0; j < 4; ++j) {
                const uint32_t* bp = b32 + (wn * 32 + j * 8 + gid) * G_STR
                                         + k16 * 8 + tig;
                b[j][0] = bp[0];
                b[j][1] = bp[4];
            }
            #pragma unroll
            for (int i = 0; i < 4; ++i)
                #pragma unroll
                for (int j = 0; j < 4; ++j)
                    mma_f16(acc[i][j], a[i], b[j]);
        }
        ++st; if (st >= 3) st -= 3;
    }
    CP_WAIT0();

    #pragma unroll
    for (int i = 0; i < 4; ++i) {
        const int row = m0 + wm * 64 + i * 16 + gid;
        #pragma unroll
        for (int j = 0; j < 4; ++j) {
            const int col = n0 + wn * 32 + j * 8 + (tig << 1);
            const float b0 = bias[col], b1 = bias[col + 1];
            float v00 = (acc[i][j][0] + b0) * scale;
            float v01 = (acc[i][j][1] + b1) * scale;
            float v10 = (acc[i][j][2] + b0) * scale;
            float v11 = (acc[i][j][3] + b1) * scale;
            if (outHalf) {
                *(uint32_t*)(Ch + (size_t)row * 1024 + col)       = pack_f16x2(v00, v01);
                *(uint32_t*)(Ch + (size_t)(row + 8) * 1024 + col) = pack_f16x2(v10, v11);
            } else {
                *(float2*)(Cf + (size_t)row * 1024 + col)       = make_float2(v00, v01);
                *(float2*)(Cf + (size_t)(row + 8) * 1024 + col) = make_float2(v10, v11);
            }
        }
    }
}

// Merged QKV: blockIdx.z selects {q, k, v}; all outputs fp16
__global__ void __launch_bounds__(256, 2)
gemm_qkv(const __half* __restrict__ xh,
         const __half* __restrict__ wq, const __half* __restrict__ wk,
         const __half* __restrict__ wv,
         const float* __restrict__ bq, const float* __restrict__ bk,
         const float* __restrict__ bv,
         __half* __restrict__ qh, __half* __restrict__ kh,
         __half* __restrict__ vh)
{
    extern __shared__ char smraw[];
    const int z = blockIdx.z;
    const __half* Wt  = (z == 0) ? wq : (z == 1) ? wk : wv;
    const float*  bia = (z == 0) ? bq : (z == 1) ? bk : bv;
    __half* outp      = (z == 0) ? qh : (z == 1) ? kh : vh;
    const float scale = (z == 0) ? 0.125f : 1.0f;
    gemm_body(smraw, xh, Wt, bia, nullptr, outp, scale, 1,
              blockIdx.x, blockIdx.y);
}

// Output projection (fp32 out)
__global__ void __launch_bounds__(256, 2)
gemm_f16(const __half* __restrict__ A, const __half* __restrict__ Wt,
         const float* __restrict__ bias, float* __restrict__ Cf, float scale)
{
    extern __shared__ char smraw[];
    gemm_body(smraw, A, Wt, bias, Cf, nullptr, scale, 0,
              blockIdx.x, blockIdx.y);
}

// ============================================================================
// FP16 flash attention (R13/R14 exact — transpose-free PV via ldmatrix.trans).
// ============================================================================
#define FQ 128
#define QK_STR 36
#define FL_SMEM ((128*QK_STR + 2*64*QK_STR + 2*64*QK_STR) * 4)  /* 55296 */

__global__ void __launch_bounds__(256, 2)
flash_tc(const __half* __restrict__ Q, const __half* __restrict__ K,
         const __half* __restrict__ V, __half* __restrict__ O)
{
    extern __shared__ char smraw[];
    const uint32_t smb    = smem_u32(smraw);
    const uint32_t ks_smb = smb + 128 * QK_STR * 4;
    const uint32_t vs_smb = ks_smb + 2 * 64 * QK_STR * 4;
    uint32_t* Qs32 = (uint32_t*)smraw;

    const int tid  = threadIdx.x;
    const int w    = tid >> 5;
    const int lane = tid & 31;
    const int gid  = lane >> 2;
    const int tig  = lane & 3;
    const int bh   = blockIdx.y;
    const int b    = bh >> 4;
    const int h    = bh & 15;
    const int q0   = blockIdx.x * FQ;

    const __half* Qg = Q + ((size_t)b * SS + q0) * NHEAD + h * HDIM;
    const __half* Kg = K + (size_t)b * SS * NHEAD + h * HDIM;
    const __half* Vg = V + (size_t)b * SS * NHEAD + h * HDIM;

    auto load_tile = [&](uint32_t dstbase, const __half* src) {
        #pragma unroll
        for (int i = 0; i < 2; ++i) {
            int idx = tid + i * 256;
            int r = idx >> 3, c = (idx & 7) << 3;
            CP16(dstbase + (uint32_t)(r * QK_STR * 4 + c * 2),
                 src + (size_t)r * NHEAD + c);
        }
    };

    load_tile(ks_smb, Kg);
    load_tile(vs_smb, Vg);
    CP_COMMIT();

    #pragma unroll
    for (int i = 0; i < 4; ++i) {
        int idx = tid + i * 256;
        int r = idx >> 3, c8 = idx & 7;
        uint4 t = *(const uint4*)(Qg + (size_t)r * NHEAD + c8 * 8);
        *(uint4*)(Qs32 + r * QK_STR + c8 * 4) = t;
    }

    float m_[2] = {-1e30f, -1e30f};
    float l_[2] = {0.f, 0.f};
    float o[8][4];
    #pragma unroll
    for (int nt = 0; nt < 8; ++nt)
        #pragma unroll
        for (int r = 0; r < 4; ++r) o[nt][r] = 0.f;

    const int qr = w * 16 + gid;

    const int arow = w * 16 + (lane & 7) + (((lane >> 3) & 1) << 3);
    const uint32_t q_lm = smb + (uint32_t)(arow * QK_STR) * 4
                              + (((lane >> 4) & 1) << 4);
    const int brow = (lane & 7) + (((lane >> 4) & 1) << 3);
    const uint32_t bcol = (((lane >> 3) & 1) << 4);
    const uint32_t k_lm0 = ks_smb + (uint32_t)(brow * QK_STR) * 4 + bcol;
    const int vrow = (lane & 7) + (((lane >> 3) & 1) << 3);
    const uint32_t vcol = (((lane >> 4) & 1) << 4);
    const uint32_t v_lm0 = vs_smb + (uint32_t)(vrow * QK_STR) * 4 + vcol;

    for (int it = 0; it < 32; ++it) {
        const int t0 = it * 64;
        CP_WAIT0();
        __syncthreads();

        if (it + 1 < 32) {
            const uint32_t alt = (uint32_t)(((it + 1) & 1) * 64 * QK_STR) * 4;
            load_tile(ks_smb + alt, Kg + (size_t)(t0 + 64) * NHEAD);
            load_tile(vs_smb + alt, Vg + (size_t)(t0 + 64) * NHEAD);
        }
        CP_COMMIT();

        const uint32_t cur = (uint32_t)((it & 1) * 64 * QK_STR) * 4;
        const uint32_t klm = k_lm0 + cur;
        const uint32_t vlm = v_lm0 + cur;

        float s[8][4];
        #pragma unroll
        for (int nt = 0; nt < 8; ++nt)
            #pragma unroll
            for (int r = 0; r < 4; ++r) s[nt][r] = 0.f;

        #pragma unroll
        for (int ks = 0; ks < 4; ++ks) {
            uint32_t a[4];
            ldm_x4(a, q_lm + ks * 32);
            #pragma unroll
            for (int p = 0; p < 4; ++p) {
                uint32_t kb[4];
                ldm_x4(kb, klm + (uint32_t)(p * 16 * QK_STR) * 4 + ks * 32);
                mma_f16(s[2 * p],     a, kb);
                mma_f16(s[2 * p + 1], a, kb + 2);
            }
        }

        #pragma unroll
        for (int hh = 0; hh < 2; ++hh) {
            const int c0 = 2 * hh, c1 = c0 + 1;
            float mt = fmaxf(s[0][c0], s[0][c1]);
            #pragma unroll
            for (int nt = 1; nt < 8; ++nt)
                mt = fmaxf(mt, fmaxf(s[nt][c0], s[nt][c1]));
            mt = fmaxf(mt, __shfl_xor_sync(0xffffffffu, mt, 1));
            mt = fmaxf(mt, __shfl_xor_sync(0xffffffffu, mt, 2));
            float mnew = fmaxf(m_[hh], mt);
            float corr = __expf(m_[hh] - mnew);
            m_[hh] = mnew;
            float ls = 0.f;
            #pragma unroll
            for (int nt = 0; nt < 8; ++nt) {
                s[nt][c0] = __expf(s[nt][c0] - mnew);
                s[nt][c1] = __expf(s[nt][c1] - mnew);
                ls += s[nt][c0] + s[nt][c1];
            }
            ls += __shfl_xor_sync(0xffffffffu, ls, 1);
            ls += __shfl_xor_sync(0xffffffffu, ls, 2);
            l_[hh] = l_[hh] * corr + ls;
            #pragma unroll
            for (int nt = 0; nt < 8; ++nt) {
                o[nt][c0] *= corr;
                o[nt][c1] *= corr;
            }
        }

        uint32_t pa[4][4];
        #pragma unroll
        for (int kc = 0; kc < 4; ++kc) {
            pa[kc][0] = pack_f16x2(s[2 * kc][0],     s[2 * kc][1]);
            pa[kc][1] = pack_f16x2(s[2 * kc][2],     s[2 * kc][3]);
            pa[kc][2] = pack_f16x2(s[2 * kc + 1][0], s[2 * kc + 1][1]);
            pa[kc][3] = pack_f16x2(s[2 * kc + 1][2], s[2 * kc + 1][3]);
        }

        #pragma unroll
        for (int kc = 0; kc < 4; ++kc) {
            #pragma unroll
            for (int p = 0; p < 4; ++p) {
                uint32_t vb[4];
                ldm_x4_t(vb, vlm + (uint32_t)(kc * 16 * QK_STR) * 4 + p * 32);
                mma_f16(o[2 * p],     pa[kc], vb);
                mma_f16(o[2 * p + 1], pa[kc], vb + 2);
            }
        }
    }

    const float inv0 = 1.f / l_[0];
    const float inv1 = 1.f / l_[1];
    __half* Og = O + ((size_t)b * SS + q0 + qr) * NHEAD + h * HDIM;
    #pragma unroll
    for (int nt = 0; nt < 8; ++nt) {
        *(uint32_t*)(Og + nt * 8 + 2 * tig) =
            pack_f16x2(o[nt][0] * inv0, o[nt][1] * inv0);
        *(uint32_t*)(Og + (size_t)8 * NHEAD + nt * 8 + 2 * tig) =
            pack_f16x2(o[nt][2] * inv1, o[nt][3] * inv1);
    }
}

// ============================================================================
extern "C" void kernel_launch(void* const* d_in, const int* in_sizes, int n_in,
                              void* d_out, int out_size)
{
    (void)in_sizes; (void)n_in; (void)out_size;
    const float* x  = (const float*)d_in[0];
    const float* Wq = (const float*)d_in[1];
    const float* bq = (const float*)d_in[2];
    const float* Wk = (const float*)d_in[3];
    const float* bk = (const float*)d_in[4];
    const float* Wv = (const float*)d_in[5];
    const float* bv = (const float*)d_in[6];
    const float* Wo = (const float*)d_in[7];
    const float* bo = (const float*)d_in[8];
    float* out = (float*)d_out;

    __half *xh, *wt, *qh, *kh, *vh, *ctxh;
    cudaGetSymbolAddress((void**)&xh,   g_xh);
    cudaGetSymbolAddress((void**)&wt,   g_wt);
    cudaGetSymbolAddress((void**)&qh,   g_qh);
    cudaGetSymbolAddress((void**)&kh,   g_kh);
    cudaGetSymbolAddress((void**)&vh,   g_vh);
    cudaGetSymbolAddress((void**)&ctxh, g_ctxh);
    __half* wqt = wt;
    __half* wkt = wt + (size_t)DD * NHEAD;
    __half* wvt = wt + 2 * (size_t)DD * NHEAD;
    __half* wot = wt + 3 * (size_t)DD * NHEAD;

    cudaFuncSetAttribute(gemm_qkv,
                         cudaFuncAttributeMaxDynamicSharedMemorySize, GSMEM);
    cudaFuncSetAttribute(gemm_f16,
                         cudaFuncAttributeMaxDynamicSharedMemorySize, GSMEM);
    cudaFuncSetAttribute(flash_tc,
                         cudaFuncAttributeMaxDynamicSharedMemorySize, FL_SMEM);

    // Merged prepass: x cvt (8192 blocks) + 4 coalesced W transposes (1024)
    prepass<<<8192 + 1024, 256>>>(x, xh, Wq, Wk, Wv, Wo, wt);

    // Merged QKV projections (128x128 tiles, BK=64); q,k,v fp16 out
    dim3 qkvgrid(NHEAD / GBN, MROWS / GBM, 3);  // (8, 64, 3)
    gemm_qkv<<<qkvgrid, 256, GSMEM>>>(xh, wqt, wkt, wvt, bq, bk, bv,
                                      qh, kh, vh);

    // FP16 flash attention (transpose-free PV via ldmatrix.trans)
    flash_tc<<<dim3(SS / FQ, BB * HH), 256, FL_SMEM>>>(qh, kh, vh, ctxh);

    // Output projection (fp32 out, BK=64)
    dim3 ggrid(NHEAD / GBN, MROWS / GBM);
    gemm_f16<<<ggrid, 256, GSMEM>>>(ctxh, wot, bo, out, 1.0f);
}

// round 16
// speedup vs baseline: 1.0574x; 1.0574x over previous
#include <cuda_runtime.h>
#include <cuda_fp16.h>
#include <cstdint>
#include <math.h>

// ============================================================================
// Problem constants
// ============================================================================
#define BB 4
#define SS 2048
#define DD 1024
#define HH 16
#define HDIM 64
#define MROWS (BB * SS)     /* 8192 */
#define NHEAD (HH * HDIM)   /* 1024 */

// Scratch (device globals: allocation-free)
__device__ __align__(16) __half g_xh[MROWS * DD];        // fp16 x
__device__ __align__(16) __half g_wt[4][DD * NHEAD];     // fp16 W^T (q,k,v,o)
__device__ __align__(16) __half g_qh[MROWS * NHEAD];     // fp16 q
__device__ __align__(16) __half g_kh[MROWS * NHEAD];     // fp16 k
__device__ __align__(16) __half g_vh[MROWS * NHEAD];     // fp16 v
__device__ __align__(16) __half g_ctxh[MROWS * NHEAD];   // fp16 ctx

// ============================================================================
// Helpers
// ============================================================================
__device__ __forceinline__ uint32_t smem_u32(const void* p) {
    uint32_t a;
    asm("{ .reg .u64 t; cvta.to.shared.u64 t, %1; cvt.u32.u64 %0, t; }"
        : "=r"(a) : "l"(p));
    return a;
}

__device__ __forceinline__ uint32_t pack_f16x2(float lo, float hi) {
    uint32_t r;
    asm("cvt.rn.f16x2.f32 %0, %1, %2;" : "=r"(r) : "f"(hi), "f"(lo));
    return r;
}

__device__ __forceinline__ void mma_f16(float* c, const uint32_t* a, const uint32_t* b) {
    asm volatile(
        "mma.sync.aligned.m16n8k16.row.col.f32.f16.f16.f32 "
        "{%0,%1,%2,%3}, {%4,%5,%6,%7}, {%8,%9}, {%0,%1,%2,%3};"
        : "+f"(c[0]), "+f"(c[1]), "+f"(c[2]), "+f"(c[3])
        : "r"(a[0]), "r"(a[1]), "r"(a[2]), "r"(a[3]), "r"(b[0]), "r"(b[1]));
}

__device__ __forceinline__ void ldm_x4(uint32_t* r, uint32_t addr) {
    asm volatile(
        "ldmatrix.sync.aligned.m8n8.x4.shared.b16 {%0,%1,%2,%3}, [%4];"
        : "=r"(r[0]), "=r"(r[1]), "=r"(r[2]), "=r"(r[3]) : "r"(addr));
}

// transposed variant: memory [k][n] row-major -> col-major B fragment
__device__ __forceinline__ void ldm_x4_t(uint32_t* r, uint32_t addr) {
    asm volatile(
        "ldmatrix.sync.aligned.m8n8.x4.trans.shared.b16 {%0,%1,%2,%3}, [%4];"
        : "=r"(r[0]), "=r"(r[1]), "=r"(r[2]), "=r"(r[3]) : "r"(addr));
}

#define CP16(dst, src) \
    asm volatile("cp.async.cg.shared.global [%0], [%1], 16;" \
        :: "r"(dst), "l"(src) : "memory")
#define CP_COMMIT() asm volatile("cp.async.commit_group;" ::: "memory")
#define CP_WAIT1()  asm volatile("cp.async.wait_group 1;" ::: "memory")
#define CP_WAIT0()  asm volatile("cp.async.wait_group 0;" ::: "memory")

// ============================================================================
// Merged prepass (single launch) — R15 exact (coalesced transposes):
//   blocks [0, 8192)        : x fp32 -> fp16 flat
//   blocks [8192, 8192+1024): W{q,k,v,o} fp32 -> fp16 transposed, 64x64 tiles
// ============================================================================
__global__ void __launch_bounds__(256)
prepass(const float* __restrict__ x, __half* __restrict__ xh,
        const float* __restrict__ Wq, const float* __restrict__ Wk,
        const float* __restrict__ Wv, const float* __restrict__ Wo,
        __half* __restrict__ wt)
{
    __shared__ float tbuf[64][65];
    int bid = blockIdx.x;
    const int tid = threadIdx.x;
    if (bid < 8192) {
        int i = bid * 256 + tid;
        float4 v = ((const float4*)x)[i];
        uint2 o;
        o.x = pack_f16x2(v.x, v.y);
        o.y = pack_f16x2(v.z, v.w);
        ((uint2*)xh)[i] = o;
        return;
    }
    bid -= 8192;
    const int wsel = bid >> 8;
    const int t    = bid & 255;
    const float* W = (wsel == 0) ? Wq : (wsel == 1) ? Wk : (wsel == 2) ? Wv : Wo;
    __half* Wt = wt + (size_t)wsel * DD * NHEAD;

    const int n0 = (t & 15) * 64, k0 = (t >> 4) * 64;
    const int tx = tid & 63, ty = tid >> 6;
    #pragma unroll
    for (int i = 0; i < 64; i += 4)
        tbuf[tx][ty + i] = W[(size_t)(k0 + ty + i) * 1024 + n0 + tx];
    __syncthreads();
    const int c = tid & 31, r = tid >> 5;
    uint32_t* Wt32 = (uint32_t*)Wt;
    #pragma unroll
    for (int i = 0; i < 64; i += 8) {
        const int nr = r + i;
        Wt32[(size_t)(n0 + nr) * 512 + (k0 >> 1) + c] =
            pack_f16x2(tbuf[nr][2 * c], tbuf[nr][2 * c + 1]);
    }
}

// ============================================================================
// FP16 GEMM core — BK=64, ldmatrix fragment loads (flash's proven mappings:
// stride 36 words identical to flash QK_STR). CTA 128x128, 8 warps (2Mx4N),
// warp tile 64x32, m16n8k16, 3 stages.
// ============================================================================
#define GBM 128
#define GBN 128
#define G_STR 36
#define G_AWORDS (GBM * G_STR)
#define G_STAGE_BYTES (2 * G_AWORDS * 4)     /* 36864 */
#define G_NSTG 3
#define GSMEM (G_NSTG * G_STAGE_BYTES)       /* 110592 */

__device__ __forceinline__ void
gemm_body(char* smraw, const __half* __restrict__ A, const __half* __restrict__ Wt,
          const float* __restrict__ bias,
          float* __restrict__ Cf, __half* __restrict__ Ch,
          float scale, int outHalf, int bx, int by)
{
    const uint32_t smb = smem_u32(smraw);

    const int tid  = threadIdx.x;
    const int lane = tid & 31;
    const int wid  = tid >> 5;
    const int wm   = wid & 1;
    const int wn   = wid >> 1;
    const int gid  = lane >> 2;
    const int tig  = lane & 3;
    const int m0   = by * GBM;
    const int n0   = bx * GBN;

    float acc[4][4][4];
    #pragma unroll
    for (int i = 0; i < 4; ++i)
        #pragma unroll
        for (int j = 0; j < 4; ++j)
            #pragma unroll
            for (int r = 0; r < 4; ++r) acc[i][j][r] = 0.f;

    const __half* Ag = A  + (size_t)m0 * 1024;
    const __half* Wg = Wt + (size_t)n0 * 1024;

    auto load_stage = [&](int s, int kt) {
        const uint32_t as = smb + (uint32_t)s * G_STAGE_BYTES;
        const uint32_t bs = as + G_AWORDS * 4;
        #pragma unroll
        for (int i = 0; i < 4; ++i) {
            int idx = tid + i * 256;
            int r = idx >> 3, c = (idx & 7) << 3;   // c in halves
            CP16(as + (uint32_t)(r * G_STR * 4 + c * 2),
                 Ag + (size_t)r * 1024 + kt * 64 + c);
            CP16(bs + (uint32_t)(r * G_STR * 4 + c * 2),
                 Wg + (size_t)r * 1024 + kt * 64 + c);
        }
    };

    // ldmatrix per-lane offsets (flash's proven Q/K mappings, stride 36)
    // A-frag: rows wm*64 + (lane&7) + ((lane>>3)&1)*8, col16 = (lane>>4)&1
    const int arow = wm * 64 + (lane & 7) + (((lane >> 3) & 1) << 3);
    const uint32_t a_off = (uint32_t)(arow * G_STR) * 4
                         + (((lane >> 4) & 1) << 4);
    // B-frag: rows wn*32 + (lane&7) + ((lane>>4)&1)*8, col16 = (lane>>3)&1
    const int brow = wn * 32 + (lane & 7) + (((lane >> 4) & 1) << 3);
    const uint32_t b_off = (uint32_t)G_AWORDS * 4
                         + (uint32_t)(brow * G_STR) * 4
                         + (((lane >> 3) & 1) << 4);

    load_stage(0, 0); CP_COMMIT();
    load_stage(1, 1); CP_COMMIT();

    int st = 0;
    for (int kt = 0; kt < 16; ++kt) {
        CP_WAIT1();
        __syncthreads();

        if (kt + 2 < 16) {
            int sn = st + 2; if (sn >= 3) sn -= 3;
            load_stage(sn, kt + 2);
        }
        CP_COMMIT();

        const uint32_t stg = smb + (uint32_t)st * G_STAGE_BYTES;
        const uint32_t alm = stg + a_off;
        const uint32_t blm = stg + b_off;

        #pragma unroll
        for (int k16 = 0; k16 < 4; ++k16) {
            uint32_t a[4][4], bb[2][4];
            #pragma unroll
            for (int i = 0; i < 4; ++i)
                ldm_x4(a[i], alm + (uint32_t)(i * 16 * G_STR) * 4 + k16 * 32);
            #pragma unroll
            for (int jp = 0; jp < 2; ++jp)
                ldm_x4(bb[jp], blm + (uint32_t)(jp * 16 * G_STR) * 4 + k16 * 32);
            #pragma unroll
            for (int i = 0; i < 4; ++i) {
                mma_f16(acc[i][0], a[i], bb[0]);
                mma_f16(acc[i][1], a[i], bb[0] + 2);
                mma_f16(acc[i][2], a[i], bb[1]);
                mma_f16(acc[i][3], a[i], bb[1] + 2);
            }
        }
        ++st; if (st >= 3) st -= 3;
    }
    CP_WAIT0();

    #pragma unroll
    for (int i = 0; i < 4; ++i) {
        const int row = m0 + wm * 64 + i * 16 + gid;
        #pragma unroll
        for (int j = 0; j < 4; ++j) {
            const int col = n0 + wn * 32 + j * 8 + (tig << 1);
            const float b0 = bias[col], b1 = bias[col + 1];
            float v00 = (acc[i][j][0] + b0) * scale;
            float v01 = (acc[i][j][1] + b1) * scale;
            float v10 = (acc[i][j][2] + b0) * scale;
            float v11 = (acc[i][j][3] + b1) * scale;
            if (outHalf) {
                *(uint32_t*)(Ch + (size_t)row * 1024 + col)       = pack_f16x2(v00, v01);
                *(uint32_t*)(Ch + (size_t)(row + 8) * 1024 + col) = pack_f16x2(v10, v11);
            } else {
                *(float2*)(Cf + (size_t)row * 1024 + col)       = make_float2(v00, v01);
                *(float2*)(Cf + (size_t)(row + 8) * 1024 + col) = make_float2(v10, v11);
            }
        }
    }
}

// Merged QKV: blockIdx.z selects {q, k, v}; all outputs fp16
__global__ void __launch_bounds__(256, 2)
gemm_qkv(const __half* __restrict__ xh,
         const __half* __restrict__ wq, const __half* __restrict__ wk,
         const __half* __restrict__ wv,
         const float* __restrict__ bq, const float* __restrict__ bk,
         const float* __restrict__ bv,
         __half* __restrict__ qh, __half* __restrict__ kh,
         __half* __restrict__ vh)
{
    extern __shared__ char smraw[];
    const int z = blockIdx.z;
    const __half* Wt  = (z == 0) ? wq : (z == 1) ? wk : wv;
    const float*  bia = (z == 0) ? bq : (z == 1) ? bk : bv;
    __half* outp      = (z == 0) ? qh : (z == 1) ? kh : vh;
    const float scale = (z == 0) ? 0.125f : 1.0f;
    gemm_body(smraw, xh, Wt, bia, nullptr, outp, scale, 1,
              blockIdx.x, blockIdx.y);
}

// Output projection (fp32 out)
__global__ void __launch_bounds__(256, 2)
gemm_f16(const __half* __restrict__ A, const __half* __restrict__ Wt,
         const float* __restrict__ bias, float* __restrict__ Cf, float scale)
{
    extern __shared__ char smraw[];
    gemm_body(smraw, A, Wt, bias, Cf, nullptr, scale, 0,
              blockIdx.x, blockIdx.y);
}

// ============================================================================
// FP16 flash attention (R13/R14 exact — transpose-free PV via ldmatrix.trans).
// ============================================================================
#define FQ 128
#define QK_STR 36
#define FL_SMEM ((128*QK_STR + 2*64*QK_STR + 2*64*QK_STR) * 4)  /* 55296 */

__global__ void __launch_bounds__(256, 2)
flash_tc(const __half* __restrict__ Q, const __half* __restrict__ K,
         const __half* __restrict__ V, __half* __restrict__ O)
{
    extern __shared__ char smraw[];
    const uint32_t smb    = smem_u32(smraw);
    const uint32_t ks_smb = smb + 128 * QK_STR * 4;
    const uint32_t vs_smb = ks_smb + 2 * 64 * QK_STR * 4;
    uint32_t* Qs32 = (uint32_t*)smraw;

    const int tid  = threadIdx.x;
    const int w    = tid >> 5;
    const int lane = tid & 31;
    const int gid  = lane >> 2;
    const int tig  = lane & 3;
    const int bh   = blockIdx.y;
    const int b    = bh >> 4;
    const int h    = bh & 15;
    const int q0   = blockIdx.x * FQ;

    const __half* Qg = Q + ((size_t)b * SS + q0) * NHEAD + h * HDIM;
    const __half* Kg = K + (size_t)b * SS * NHEAD + h * HDIM;
    const __half* Vg = V + (size_t)b * SS * NHEAD + h * HDIM;

    auto load_tile = [&](uint32_t dstbase, const __half* src) {
        #pragma unroll
        for (int i = 0; i < 2; ++i) {
            int idx = tid + i * 256;
            int r = idx >> 3, c = (idx & 7) << 3;
            CP16(dstbase + (uint32_t)(r * QK_STR * 4 + c * 2),
                 src + (size_t)r * NHEAD + c);
        }
    };

    load_tile(ks_smb, Kg);
    load_tile(vs_smb, Vg);
    CP_COMMIT();

    #pragma unroll
    for (int i = 0; i < 4; ++i) {
        int idx = tid + i * 256;
        int r = idx >> 3, c8 = idx & 7;
        uint4 t = *(const uint4*)(Qg + (size_t)r * NHEAD + c8 * 8);
        *(uint4*)(Qs32 + r * QK_STR + c8 * 4) = t;
    }

    float m_[2] = {-1e30f, -1e30f};
    float l_[2] = {0.f, 0.f};
    float o[8][4];
    #pragma unroll
    for (int nt = 0; nt < 8; ++nt)
        #pragma unroll
        for (int r = 0; r < 4; ++r) o[nt][r] = 0.f;

    const int qr = w * 16 + gid;

    const int arow = w * 16 + (lane & 7) + (((lane >> 3) & 1) << 3);
    const uint32_t q_lm = smb + (uint32_t)(arow * QK_STR) * 4
                              + (((lane >> 4) & 1) << 4);
    const int brow = (lane & 7) + (((lane >> 4) & 1) << 3);
    const uint32_t bcol = (((lane >> 3) & 1) << 4);
    const uint32_t k_lm0 = ks_smb + (uint32_t)(brow * QK_STR) * 4 + bcol;
    const int vrow = (lane & 7) + (((lane >> 3) & 1) << 3);
    const uint32_t vcol = (((lane >> 4) & 1) << 4);
    const uint32_t v_lm0 = vs_smb + (uint32_t)(vrow * QK_STR) * 4 + vcol;

    for (int it = 0; it < 32; ++it) {
        const int t0 = it * 64;
        CP_WAIT0();
        __syncthreads();

        if (it + 1 < 32) {
            const uint32_t alt = (uint32_t)(((it + 1) & 1) * 64 * QK_STR) * 4;
            load_tile(ks_smb + alt, Kg + (size_t)(t0 + 64) * NHEAD);
            load_tile(vs_smb + alt, Vg + (size_t)(t0 + 64) * NHEAD);
        }
        CP_COMMIT();

        const uint32_t cur = (uint32_t)((it & 1) * 64 * QK_STR) * 4;
        const uint32_t klm = k_lm0 + cur;
        const uint32_t vlm = v_lm0 + cur;

        float s[8][4];
        #pragma unroll
        for (int nt = 0; nt < 8; ++nt)
            #pragma unroll
            for (int r = 0; r < 4; ++r) s[nt][r] = 0.f;

        #pragma unroll
        for (int ks = 0; ks < 4; ++ks) {
            uint32_t a[4];
            ldm_x4(a, q_lm + ks * 32);
            #pragma unroll
            for (int p = 0; p < 4; ++p) {
                uint32_t kb[4];
                ldm_x4(kb, klm + (uint32_t)(p * 16 * QK_STR) * 4 + ks * 32);
                mma_f16(s[2 * p],     a, kb);
                mma_f16(s[2 * p + 1], a, kb + 2);
            }
        }

        #pragma unroll
        for (int hh = 0; hh < 2; ++hh) {
            const int c0 = 2 * hh, c1 = c0 + 1;
            float mt = fmaxf(s[0][c0], s[0][c1]);
            #pragma unroll
            for (int nt = 1; nt < 8; ++nt)
                mt = fmaxf(mt, fmaxf(s[nt][c0], s[nt][c1]));
            mt = fmaxf(mt, __shfl_xor_sync(0xffffffffu, mt, 1));
            mt = fmaxf(mt, __shfl_xor_sync(0xffffffffu, mt, 2));
            float mnew = fmaxf(m_[hh], mt);
            float corr = __expf(m_[hh] - mnew);
            m_[hh] = mnew;
            float ls = 0.f;
            #pragma unroll
            for (int nt = 0; nt < 8; ++nt) {
                s[nt][c0] = __expf(s[nt][c0] - mnew);
                s[nt][c1] = __expf(s[nt][c1] - mnew);
                ls += s[nt][c0] + s[nt][c1];
            }
            ls += __shfl_xor_sync(0xffffffffu, ls, 1);
            ls += __shfl_xor_sync(0xffffffffu, ls, 2);
            l_[hh] = l_[hh] * corr + ls;
            #pragma unroll
            for (int nt = 0; nt < 8; ++nt) {
                o[nt][c0] *= corr;
                o[nt][c1] *= corr;
            }
        }

        uint32_t pa[4][4];
        #pragma unroll
        for (int kc = 0; kc < 4; ++kc) {
            pa[kc][0] = pack_f16x2(s[2 * kc][0],     s[2 * kc][1]);
            pa[kc][1] = pack_f16x2(s[2 * kc][2],     s[2 * kc][3]);
            pa[kc][2] = pack_f16x2(s[2 * kc + 1][0], s[2 * kc + 1][1]);
            pa[kc][3] = pack_f16x2(s[2 * kc + 1][2], s[2 * kc + 1][3]);
        }

        #pragma unroll
        for (int kc = 0; kc < 4; ++kc) {
            #pragma unroll
            for (int p = 0; p < 4; ++p) {
                uint32_t vb[4];
                ldm_x4_t(vb, vlm + (uint32_t)(kc * 16 * QK_STR) * 4 + p * 32);
                mma_f16(o[2 * p],     pa[kc], vb);
                mma_f16(o[2 * p + 1], pa[kc], vb + 2);
            }
        }
    }

    const float inv0 = 1.f / l_[0];
    const float inv1 = 1.f / l_[1];
    __half* Og = O + ((size_t)b * SS + q0 + qr) * NHEAD + h * HDIM;
    #pragma unroll
    for (int nt = 0; nt < 8; ++nt) {
        *(uint32_t*)(Og + nt * 8 + 2 * tig) =
            pack_f16x2(o[nt][0] * inv0, o[nt][1] * inv0);
        *(uint32_t*)(Og + (size_t)8 * NHEAD + nt * 8 + 2 * tig) =
            pack_f16x2(o[nt][2] * inv1, o[nt][3] * inv1);
    }
}

// ============================================================================
extern "C" void kernel_launch(void* const* d_in, const int* in_sizes, int n_in,
                              void* d_out, int out_size)
{
    (void)in_sizes; (void)n_in; (void)out_size;
    const float* x  = (const float*)d_in[0];
    const float* Wq = (const float*)d_in[1];
    const float* bq = (const float*)d_in[2];
    const float* Wk = (const float*)d_in[3];
    const float* bk = (const float*)d_in[4];
    const float* Wv = (const float*)d_in[5];
    const float* bv = (const float*)d_in[6];
    const float* Wo = (const float*)d_in[7];
    const float* bo = (const float*)d_in[8];
    float* out = (float*)d_out;

    __half *xh, *wt, *qh, *kh, *vh, *ctxh;
    cudaGetSymbolAddress((void**)&xh,   g_xh);
    cudaGetSymbolAddress((void**)&wt,   g_wt);
    cudaGetSymbolAddress((void**)&qh,   g_qh);
    cudaGetSymbolAddress((void**)&kh,   g_kh);
    cudaGetSymbolAddress((void**)&vh,   g_vh);
    cudaGetSymbolAddress((void**)&ctxh, g_ctxh);
    __half* wqt = wt;
    __half* wkt = wt + (size_t)DD * NHEAD;
    __half* wvt = wt + 2 * (size_t)DD * NHEAD;
    __half* wot = wt + 3 * (size_t)DD * NHEAD;

    cudaFuncSetAttribute(gemm_qkv,
                         cudaFuncAttributeMaxDynamicSharedMemorySize, GSMEM);
    cudaFuncSetAttribute(gemm_f16,
                         cudaFuncAttributeMaxDynamicSharedMemorySize, GSMEM);
    cudaFuncSetAttribute(flash_tc,
                         cudaFuncAttributeMaxDynamicSharedMemorySize, FL_SMEM);

    // Merged prepass: x cvt (8192 blocks) + 4 coalesced W transposes (1024)
    prepass<<<8192 + 1024, 256>>>(x, xh, Wq, Wk, Wv, Wo, wt);

    // Merged QKV projections (128x128 tiles, BK=64, ldmatrix frags)
    dim3 qkvgrid(NHEAD / GBN, MROWS / GBM, 3);  // (8, 64, 3)
    gemm_qkv<<<qkvgrid, 256, GSMEM>>>(xh, wqt, wkt, wvt, bq, bk, bv,
                                      qh, kh, vh);

    // FP16 flash attention (transpose-free PV via ldmatrix.trans)
    flash_tc<<<dim3(SS / FQ, BB * HH), 256, FL_SMEM>>>(qh, kh, vh, ctxh);

    // Output projection (fp32 out, BK=64, ldmatrix frags)
    dim3 ggrid(NHEAD / GBN, MROWS / GBM);
    gemm_f16<<<ggrid, 256, GSMEM>>>(ctxh, wot, bo, out, 1.0f);
}

// round 17
// speedup vs baseline: 1.0681x; 1.0101x over previous
#include <cuda_runtime.h>
#include <cuda_fp16.h>
#include <cstdint>
#include <math.h>

// ============================================================================
// Problem constants
// ============================================================================
#define BB 4
#define SS 2048
#define DD 1024
#define HH 16
#define HDIM 64
#define MROWS (BB * SS)     /* 8192 */
#define NHEAD (HH * HDIM)   /* 1024 */

// Scratch (device globals: allocation-free)
__device__ __align__(16) __half g_xh[MROWS * DD];        // fp16 x
__device__ __align__(16) __half g_wt[4][DD * NHEAD];     // fp16 W^T (q,k,v,o)
__device__ __align__(16) __half g_qh[MROWS * NHEAD];     // fp16 q
__device__ __align__(16) __half g_kh[MROWS * NHEAD];     // fp16 k
__device__ __align__(16) __half g_vh[MROWS * NHEAD];     // fp16 v
__device__ __align__(16) __half g_ctxh[MROWS * NHEAD];   // fp16 ctx

// ============================================================================
// Helpers
// ============================================================================
__device__ __forceinline__ uint32_t smem_u32(const void* p) {
    uint32_t a;
    asm("{ .reg .u64 t; cvta.to.shared.u64 t, %1; cvt.u32.u64 %0, t; }"
        : "=r"(a) : "l"(p));
    return a;
}

__device__ __forceinline__ uint32_t pack_f16x2(float lo, float hi) {
    uint32_t r;
    asm("cvt.rn.f16x2.f32 %0, %1, %2;" : "=r"(r) : "f"(hi), "f"(lo));
    return r;
}

__device__ __forceinline__ void mma_f16(float* c, const uint32_t* a, const uint32_t* b) {
    asm volatile(
        "mma.sync.aligned.m16n8k16.row.col.f32.f16.f16.f32 "
        "{%0,%1,%2,%3}, {%4,%5,%6,%7}, {%8,%9}, {%0,%1,%2,%3};"
        : "+f"(c[0]), "+f"(c[1]), "+f"(c[2]), "+f"(c[3])
        : "r"(a[0]), "r"(a[1]), "r"(a[2]), "r"(a[3]), "r"(b[0]), "r"(b[1]));
}

__device__ __forceinline__ void ldm_x4(uint32_t* r, uint32_t addr) {
    asm volatile(
        "ldmatrix.sync.aligned.m8n8.x4.shared.b16 {%0,%1,%2,%3}, [%4];"
        : "=r"(r[0]), "=r"(r[1]), "=r"(r[2]), "=r"(r[3]) : "r"(addr));
}

// transposed variant: memory [k][n] row-major -> col-major B fragment
__device__ __forceinline__ void ldm_x4_t(uint32_t* r, uint32_t addr) {
    asm volatile(
        "ldmatrix.sync.aligned.m8n8.x4.trans.shared.b16 {%0,%1,%2,%3}, [%4];"
        : "=r"(r[0]), "=r"(r[1]), "=r"(r[2]), "=r"(r[3]) : "r"(addr));
}

#define CP16(dst, src) \
    asm volatile("cp.async.cg.shared.global [%0], [%1], 16;" \
        :: "r"(dst), "l"(src) : "memory")
#define CP_COMMIT() asm volatile("cp.async.commit_group;" ::: "memory")
#define CP_WAIT1()  asm volatile("cp.async.wait_group 1;" ::: "memory")
#define CP_WAIT0()  asm volatile("cp.async.wait_group 0;" ::: "memory")

// ============================================================================
// Merged prepass (single launch) — R16 exact:
//   blocks [0, 8192)        : x fp32 -> fp16 flat
//   blocks [8192, 8192+1024): W{q,k,v,o} fp32 -> fp16 transposed, 64x64 tiles
// ============================================================================
__global__ void __launch_bounds__(256)
prepass(const float* __restrict__ x, __half* __restrict__ xh,
        const float* __restrict__ Wq, const float* __restrict__ Wk,
        const float* __restrict__ Wv, const float* __restrict__ Wo,
        __half* __restrict__ wt)
{
    __shared__ float tbuf[64][65];
    int bid = blockIdx.x;
    const int tid = threadIdx.x;
    if (bid < 8192) {
        int i = bid * 256 + tid;
        float4 v = ((const float4*)x)[i];
        uint2 o;
        o.x = pack_f16x2(v.x, v.y);
        o.y = pack_f16x2(v.z, v.w);
        ((uint2*)xh)[i] = o;
        return;
    }
    bid -= 8192;
    const int wsel = bid >> 8;
    const int t    = bid & 255;
    const float* W = (wsel == 0) ? Wq : (wsel == 1) ? Wk : (wsel == 2) ? Wv : Wo;
    __half* Wt = wt + (size_t)wsel * DD * NHEAD;

    const int n0 = (t & 15) * 64, k0 = (t >> 4) * 64;
    const int tx = tid & 63, ty = tid >> 6;
    #pragma unroll
    for (int i = 0; i < 64; i += 4)
        tbuf[tx][ty + i] = W[(size_t)(k0 + ty + i) * 1024 + n0 + tx];
    __syncthreads();
    const int c = tid & 31, r = tid >> 5;
    uint32_t* Wt32 = (uint32_t*)Wt;
    #pragma unroll
    for (int i = 0; i < 64; i += 8) {
        const int nr = r + i;
        Wt32[(size_t)(n0 + nr) * 512 + (k0 >> 1) + c] =
            pack_f16x2(tbuf[nr][2 * c], tbuf[nr][2 * c + 1]);
    }
}

// ============================================================================
// FP16 GEMM core — R16 exact (BK=64, ldmatrix fragment loads).
// CTA 128x128, 8 warps (2Mx4N), warp tile 64x32, m16n8k16, 3 stages.
// ============================================================================
#define GBM 128
#define GBN 128
#define G_STR 36
#define G_AWORDS (GBM * G_STR)
#define G_STAGE_BYTES (2 * G_AWORDS * 4)     /* 36864 */
#define G_NSTG 3
#define GSMEM (G_NSTG * G_STAGE_BYTES)       /* 110592 */

__device__ __forceinline__ void
gemm_body(char* smraw, const __half* __restrict__ A, const __half* __restrict__ Wt,
          const float* __restrict__ bias,
          float* __restrict__ Cf, __half* __restrict__ Ch,
          float scale, int outHalf, int bx, int by)
{
    const uint32_t smb = smem_u32(smraw);

    const int tid  = threadIdx.x;
    const int lane = tid & 31;
    const int wid  = tid >> 5;
    const int wm   = wid & 1;
    const int wn   = wid >> 1;
    const int gid  = lane >> 2;
    const int tig  = lane & 3;
    const int m0   = by * GBM;
    const int n0   = bx * GBN;

    float acc[4][4][4];
    #pragma unroll
    for (int i = 0; i < 4; ++i)
        #pragma unroll
        for (int j = 0; j < 4; ++j)
            #pragma unroll
            for (int r = 0; r < 4; ++r) acc[i][j][r] = 0.f;

    const __half* Ag = A  + (size_t)m0 * 1024;
    const __half* Wg = Wt + (size_t)n0 * 1024;

    auto load_stage = [&](int s, int kt) {
        const uint32_t as = smb + (uint32_t)s * G_STAGE_BYTES;
        const uint32_t bs = as + G_AWORDS * 4;
        #pragma unroll
        for (int i = 0; i < 4; ++i) {
            int idx = tid + i * 256;
            int r = idx >> 3, c = (idx & 7) << 3;   // c in halves
            CP16(as + (uint32_t)(r * G_STR * 4 + c * 2),
                 Ag + (size_t)r * 1024 + kt * 64 + c);
            CP16(bs + (uint32_t)(r * G_STR * 4 + c * 2),
                 Wg + (size_t)r * 1024 + kt * 64 + c);
        }
    };

    const int arow = wm * 64 + (lane & 7) + (((lane >> 3) & 1) << 3);
    const uint32_t a_off = (uint32_t)(arow * G_STR) * 4
                         + (((lane >> 4) & 1) << 4);
    const int brow = wn * 32 + (lane & 7) + (((lane >> 4) & 1) << 3);
    const uint32_t b_off = (uint32_t)G_AWORDS * 4
                         + (uint32_t)(brow * G_STR) * 4
                         + (((lane >> 3) & 1) << 4);

    load_stage(0, 0); CP_COMMIT();
    load_stage(1, 1); CP_COMMIT();

    int st = 0;
    for (int kt = 0; kt < 16; ++kt) {
        CP_WAIT1();
        __syncthreads();

        if (kt + 2 < 16) {
            int sn = st + 2; if (sn >= 3) sn -= 3;
            load_stage(sn, kt + 2);
        }
        CP_COMMIT();

        const uint32_t stg = smb + (uint32_t)st * G_STAGE_BYTES;
        const uint32_t alm = stg + a_off;
        const uint32_t blm = stg + b_off;

        #pragma unroll
        for (int k16 = 0; k16 < 4; ++k16) {
            uint32_t a[4][4], bb[2][4];
            #pragma unroll
            for (int i = 0; i < 4; ++i)
                ldm_x4(a[i], alm + (uint32_t)(i * 16 * G_STR) * 4 + k16 * 32);
            #pragma unroll
            for (int jp = 0; jp < 2; ++jp)
                ldm_x4(bb[jp], blm + (uint32_t)(jp * 16 * G_STR) * 4 + k16 * 32);
            #pragma unroll
            for (int i = 0; i < 4; ++i) {
                mma_f16(acc[i][0], a[i], bb[0]);
                mma_f16(acc[i][1], a[i], bb[0] + 2);
                mma_f16(acc[i][2], a[i], bb[1]);
                mma_f16(acc[i][3], a[i], bb[1] + 2);
            }
        }
        ++st; if (st >= 3) st -= 3;
    }
    CP_WAIT0();

    #pragma unroll
    for (int i = 0; i < 4; ++i) {
        const int row = m0 + wm * 64 + i * 16 + gid;
        #pragma unroll
        for (int j = 0; j < 4; ++j) {
            const int col = n0 + wn * 32 + j * 8 + (tig << 1);
            const float b0 = bias[col], b1 = bias[col + 1];
            float v00 = (acc[i][j][0] + b0) * scale;
            float v01 = (acc[i][j][1] + b1) * scale;
            float v10 = (acc[i][j][2] + b0) * scale;
            float v11 = (acc[i][j][3] + b1) * scale;
            if (outHalf) {
                *(uint32_t*)(Ch + (size_t)row * 1024 + col)       = pack_f16x2(v00, v01);
                *(uint32_t*)(Ch + (size_t)(row + 8) * 1024 + col) = pack_f16x2(v10, v11);
            } else {
                *(float2*)(Cf + (size_t)row * 1024 + col)       = make_float2(v00, v01);
                *(float2*)(Cf + (size_t)(row + 8) * 1024 + col) = make_float2(v10, v11);
            }
        }
    }
}

// Merged QKV: blockIdx.z selects {q, k, v}; all outputs fp16
__global__ void __launch_bounds__(256, 2)
gemm_qkv(const __half* __restrict__ xh,
         const __half* __restrict__ wq, const __half* __restrict__ wk,
         const __half* __restrict__ wv,
         const float* __restrict__ bq, const float* __restrict__ bk,
         const float* __restrict__ bv,
         __half* __restrict__ qh, __half* __restrict__ kh,
         __half* __restrict__ vh)
{
    extern __shared__ char smraw[];
    const int z = blockIdx.z;
    const __half* Wt  = (z == 0) ? wq : (z == 1) ? wk : wv;
    const float*  bia = (z == 0) ? bq : (z == 1) ? bk : bv;
    __half* outp      = (z == 0) ? qh : (z == 1) ? kh : vh;
    const float scale = (z == 0) ? 0.125f : 1.0f;
    gemm_body(smraw, xh, Wt, bia, nullptr, outp, scale, 1,
              blockIdx.x, blockIdx.y);
}

// Output projection (fp32 out)
__global__ void __launch_bounds__(256, 2)
gemm_f16(const __half* __restrict__ A, const __half* __restrict__ Wt,
         const float* __restrict__ bias, float* __restrict__ Cf, float scale)
{
    extern __shared__ char smraw[];
    gemm_body(smraw, A, Wt, bias, Cf, nullptr, scale, 0,
              blockIdx.x, blockIdx.y);
}

// ============================================================================
// FP16 flash attention — 128-key iterations (16 outer iters, one barrier +
// one cp.async wait each; two back-to-back 64-key passes inside).
// Keys processed in identical order as the 64-key version -> bit-identical.
// ============================================================================
#define FQ 128
#define QK_STR 36
// Qs 128x36 + Ks 2x128x36 + Vs 2x128x36 (u32 words)
#define FL_SMEM ((128*QK_STR + 2*128*QK_STR + 2*128*QK_STR) * 4)  /* 92160 */

__global__ void __launch_bounds__(256, 2)
flash_tc(const __half* __restrict__ Q, const __half* __restrict__ K,
         const __half* __restrict__ V, __half* __restrict__ O)
{
    extern __shared__ char smraw[];
    const uint32_t smb    = smem_u32(smraw);
    const uint32_t ks_smb = smb + 128 * QK_STR * 4;
    const uint32_t vs_smb = ks_smb + 2 * 128 * QK_STR * 4;
    uint32_t* Qs32 = (uint32_t*)smraw;

    const int tid  = threadIdx.x;
    const int w    = tid >> 5;
    const int lane = tid & 31;
    const int gid  = lane >> 2;
    const int tig  = lane & 3;
    const int bh   = blockIdx.y;
    const int b    = bh >> 4;
    const int h    = bh & 15;
    const int q0   = blockIdx.x * FQ;

    const __half* Qg = Q + ((size_t)b * SS + q0) * NHEAD + h * HDIM;
    const __half* Kg = K + (size_t)b * SS * NHEAD + h * HDIM;
    const __half* Vg = V + (size_t)b * SS * NHEAD + h * HDIM;

    // 128x64 fp16 tile = 16KB = 1024 chunks = 4/thread
    auto load_tile128 = [&](uint32_t dstbase, const __half* src) {
        #pragma unroll
        for (int i = 0; i < 4; ++i) {
            int idx = tid + i * 256;
            int r = idx >> 3, c = (idx & 7) << 3;
            CP16(dstbase + (uint32_t)(r * QK_STR * 4 + c * 2),
                 src + (size_t)r * NHEAD + c);
        }
    };

    // Prologue: K(0), V(0) (128 rows each) -> buffer 0
    load_tile128(ks_smb, Kg);
    load_tile128(vs_smb, Vg);
    CP_COMMIT();

    // Load Q tile (128 x 64 fp16) while DMA flies
    #pragma unroll
    for (int i = 0; i < 4; ++i) {
        int idx = tid + i * 256;
        int r = idx >> 3, c8 = idx & 7;
        uint4 t = *(const uint4*)(Qg + (size_t)r * NHEAD + c8 * 8);
        *(uint4*)(Qs32 + r * QK_STR + c8 * 4) = t;
    }

    float m_[2] = {-1e30f, -1e30f};
    float l_[2] = {0.f, 0.f};
    float o[8][4];
    #pragma unroll
    for (int nt = 0; nt < 8; ++nt)
        #pragma unroll
        for (int r = 0; r < 4; ++r) o[nt][r] = 0.f;

    const int qr = w * 16 + gid;

    const int arow = w * 16 + (lane & 7) + (((lane >> 3) & 1) << 3);
    const uint32_t q_lm = smb + (uint32_t)(arow * QK_STR) * 4
                              + (((lane >> 4) & 1) << 4);
    const int brow = (lane & 7) + (((lane >> 4) & 1) << 3);
    const uint32_t bcol = (((lane >> 3) & 1) << 4);
    const uint32_t k_lm0 = ks_smb + (uint32_t)(brow * QK_STR) * 4 + bcol;
    const int vrow = (lane & 7) + (((lane >> 3) & 1) << 3);
    const uint32_t vcol = (((lane >> 4) & 1) << 4);
    const uint32_t v_lm0 = vs_smb + (uint32_t)(vrow * QK_STR) * 4 + vcol;

    for (int it = 0; it < 16; ++it) {
        const int t0 = it * 128;
        CP_WAIT0();          // K(it), V(it) arrived
        __syncthreads();     // visible; prev iter's reads of alt buf retired

        // Prefetch next 128-row K,V into alternate buffers
        if (it + 1 < 16) {
            const uint32_t alt = (uint32_t)(((it + 1) & 1) * 128 * QK_STR) * 4;
            load_tile128(ks_smb + alt, Kg + (size_t)(t0 + 128) * NHEAD);
            load_tile128(vs_smb + alt, Vg + (size_t)(t0 + 128) * NHEAD);
        }
        CP_COMMIT();

        const uint32_t cur = (uint32_t)((it & 1) * 128 * QK_STR) * 4;

        #pragma unroll
        for (int sub = 0; sub < 2; ++sub) {
            const uint32_t soff = cur + (uint32_t)(sub * 64 * QK_STR) * 4;
            const uint32_t klm = k_lm0 + soff;
            const uint32_t vlm = v_lm0 + soff;

            // S = Q K^T (fp16 mma, ldmatrix frags)
            float s[8][4];
            #pragma unroll
            for (int nt = 0; nt < 8; ++nt)
                #pragma unroll
                for (int r = 0; r < 4; ++r) s[nt][r] = 0.f;

            #pragma unroll
            for (int ks = 0; ks < 4; ++ks) {
                uint32_t a[4];
                ldm_x4(a, q_lm + ks * 32);
                #pragma unroll
                for (int p = 0; p < 4; ++p) {
                    uint32_t kb[4];
                    ldm_x4(kb, klm + (uint32_t)(p * 16 * QK_STR) * 4 + ks * 32);
                    mma_f16(s[2 * p],     a, kb);
                    mma_f16(s[2 * p + 1], a, kb + 2);
                }
            }

            // Online softmax per row-half
            #pragma unroll
            for (int hh = 0; hh < 2; ++hh) {
                const int c0 = 2 * hh, c1 = c0 + 1;
                float mt = fmaxf(s[0][c0], s[0][c1]);
                #pragma unroll
                for (int nt = 1; nt < 8; ++nt)
                    mt = fmaxf(mt, fmaxf(s[nt][c0], s[nt][c1]));
                mt = fmaxf(mt, __shfl_xor_sync(0xffffffffu, mt, 1));
                mt = fmaxf(mt, __shfl_xor_sync(0xffffffffu, mt, 2));
                float mnew = fmaxf(m_[hh], mt);
                float corr = __expf(m_[hh] - mnew);
                m_[hh] = mnew;
                float ls = 0.f;
                #pragma unroll
                for (int nt = 0; nt < 8; ++nt) {
                    s[nt][c0] = __expf(s[nt][c0] - mnew);
                    s[nt][c1] = __expf(s[nt][c1] - mnew);
                    ls += s[nt][c0] + s[nt][c1];
                }
                ls += __shfl_xor_sync(0xffffffffu, ls, 1);
                ls += __shfl_xor_sync(0xffffffffu, ls, 2);
                l_[hh] = l_[hh] * corr + ls;
                #pragma unroll
                for (int nt = 0; nt < 8; ++nt) {
                    o[nt][c0] *= corr;
                    o[nt][c1] *= corr;
                }
            }

            // Pack P: S C-frag -> fp16 A-frag (registers only)
            uint32_t pa[4][4];
            #pragma unroll
            for (int kc = 0; kc < 4; ++kc) {
                pa[kc][0] = pack_f16x2(s[2 * kc][0],     s[2 * kc][1]);
                pa[kc][1] = pack_f16x2(s[2 * kc][2],     s[2 * kc][3]);
                pa[kc][2] = pack_f16x2(s[2 * kc + 1][0], s[2 * kc + 1][1]);
                pa[kc][3] = pack_f16x2(s[2 * kc + 1][2], s[2 * kc + 1][3]);
            }

            // O += P V (fp16 mma, ldmatrix.trans B-frags from natural V)
            #pragma unroll
            for (int kc = 0; kc < 4; ++kc) {
                #pragma unroll
                for (int p = 0; p < 4; ++p) {
                    uint32_t vb[4];
                    ldm_x4_t(vb, vlm + (uint32_t)(kc * 16 * QK_STR) * 4 + p * 32);
                    mma_f16(o[2 * p],     pa[kc], vb);
                    mma_f16(o[2 * p + 1], pa[kc], vb + 2);
                }
            }
        }
    }

    const float inv0 = 1.f / l_[0];
    const float inv1 = 1.f / l_[1];
    __half* Og = O + ((size_t)b * SS + q0 + qr) * NHEAD + h * HDIM;
    #pragma unroll
    for (int nt = 0; nt < 8; ++nt) {
        *(uint32_t*)(Og + nt * 8 + 2 * tig) =
            pack_f16x2(o[nt][0] * inv0, o[nt][1] * inv0);
        *(uint32_t*)(Og + (size_t)8 * NHEAD + nt * 8 + 2 * tig) =
            pack_f16x2(o[nt][2] * inv1, o[nt][3] * inv1);
    }
}

// ============================================================================
extern "C" void kernel_launch(void* const* d_in, const int* in_sizes, int n_in,
                              void* d_out, int out_size)
{
    (void)in_sizes; (void)n_in; (void)out_size;
    const float* x  = (const float*)d_in[0];
    const float* Wq = (const float*)d_in[1];
    const float* bq = (const float*)d_in[2];
    const float* Wk = (const float*)d_in[3];
    const float* bk = (const float*)d_in[4];
    const float* Wv = (const float*)d_in[5];
    const float* bv = (const float*)d_in[6];
    const float* Wo = (const float*)d_in[7];
    const float* bo = (const float*)d_in[8];
    float* out = (float*)d_out;

    __half *xh, *wt, *qh, *kh, *vh, *ctxh;
    cudaGetSymbolAddress((void**)&xh,   g_xh);
    cudaGetSymbolAddress((void**)&wt,   g_wt);
    cudaGetSymbolAddress((void**)&qh,   g_qh);
    cudaGetSymbolAddress((void**)&kh,   g_kh);
    cudaGetSymbolAddress((void**)&vh,   g_vh);
    cudaGetSymbolAddress((void**)&ctxh, g_ctxh);
    __half* wqt = wt;
    __half* wkt = wt + (size_t)DD * NHEAD;
    __half* wvt = wt + 2 * (size_t)DD * NHEAD;
    __half* wot = wt + 3 * (size_t)DD * NHEAD;

    cudaFuncSetAttribute(gemm_qkv,
                         cudaFuncAttributeMaxDynamicSharedMemorySize, GSMEM);
    cudaFuncSetAttribute(gemm_f16,
                         cudaFuncAttributeMaxDynamicSharedMemorySize, GSMEM);
    cudaFuncSetAttribute(flash_tc,
                         cudaFuncAttributeMaxDynamicSharedMemorySize, FL_SMEM);

    // Merged prepass: x cvt (8192 blocks) + 4 coalesced W transposes (1024)
    prepass<<<8192 + 1024, 256>>>(x, xh, Wq, Wk, Wv, Wo, wt);

    // Merged QKV projections (128x128 tiles, BK=64, ldmatrix frags)
    dim3 qkvgrid(NHEAD / GBN, MROWS / GBM, 3);  // (8, 64, 3)
    gemm_qkv<<<qkvgrid, 256, GSMEM>>>(xh, wqt, wkt, wvt, bq, bk, bv,
                                      qh, kh, vh);

    // FP16 flash attention (128-key iterations)
    flash_tc<<<dim3(SS / FQ, BB * HH), 256, FL_SMEM>>>(qh, kh, vh, ctxh);

    // Output projection (fp32 out, BK=64, ldmatrix frags)
    dim3 ggrid(NHEAD / GBN, MROWS / GBM);
    gemm_f16<<<ggrid, 256, GSMEM>>>(ctxh, wot, bo, out, 1.0f);
}